// round 8
// baseline (speedup 1.0000x reference)
#include <cuda_runtime.h>

typedef unsigned long long u64;

// Problem constants
#define IHW   32
#define IC    8
#define OC    16
#define PP    5
#define IDIM  72            // IC*3*3
#define NROWS 8192          // N*OH*OW = 8*32*32
#define RECF  52            // floats per (i,o) record: 26 duplicated pairs
#define RECQ  13            // ulonglong2 per record

// Precomputed per-(i,o) params, duplicated pairs for f32x2 consumption.
// pair order: l2, -z0..-z4, a'0..a'4 (= sqrt(l2)*alpha),
//             L'00..L'44 (= sqrt(l2)*Linv lower tri row-major, 15 vals)
__device__ float g_params[IDIM * OC * RECF];

// ---------------------------------------------------------------------------
// f32x2 helpers (sm_103a packed fp32)
// ---------------------------------------------------------------------------
__device__ __forceinline__ u64 pk2(float a, float b) {
    u64 r; asm("mov.b64 %0, {%1, %2};" : "=l"(r) : "f"(a), "f"(b)); return r;
}
__device__ __forceinline__ void upk2(u64 v, float& a, float& b) {
    asm("mov.b64 {%0, %1}, %2;" : "=f"(a), "=f"(b) : "l"(v));
}
__device__ __forceinline__ u64 fma2(u64 a, u64 b, u64 c) {
    u64 r; asm("fma.rn.f32x2 %0, %1, %2, %3;" : "=l"(r) : "l"(a), "l"(b), "l"(c)); return r;
}
__device__ __forceinline__ u64 mul2(u64 a, u64 b) {
    u64 r; asm("mul.rn.f32x2 %0, %1, %2;" : "=l"(r) : "l"(a), "l"(b)); return r;
}
__device__ __forceinline__ u64 add2(u64 a, u64 b) {
    u64 r; asm("add.rn.f32x2 %0, %1, %2;" : "=l"(r) : "l"(a), "l"(b)); return r;
}
__device__ __forceinline__ u64 ex2_2(u64 v) {
    float a, b; upk2(v, a, b);
    asm("ex2.approx.ftz.f32 %0, %0;" : "+f"(a));
    asm("ex2.approx.ftz.f32 %0, %0;" : "+f"(b));
    return pk2(a, b);
}
__device__ __forceinline__ u64 rsqrt_2(u64 v) {
    float a, b; upk2(v, a, b);
    asm("rsqrt.approx.ftz.f32 %0, %0;" : "+f"(a));
    asm("rsqrt.approx.ftz.f32 %0, %0;" : "+f"(b));
    return pk2(a, b);
}

// fp64 reciprocal-sqrt without divisions: float MUFU seed + 2 Newton iters
__device__ __forceinline__ double drsqrt(double x)
{
    float xf = (float)x, yf;
    asm("rsqrt.approx.ftz.f32 %0, %1;" : "=f"(yf) : "f"(xf));
    double y = (double)yf;
    y = y * (1.5 - 0.5 * x * y * y);
    y = y * (1.5 - 0.5 * x * y * y);
    return y;
}

// ---------------------------------------------------------------------------
// Kernel 1: per-neuron precompute.
// fp32 softplus + K-matrix exps (matches fp32 reference K); fp64 5x5 solves.
// ---------------------------------------------------------------------------
__global__ void gp_precompute(const float* __restrict__ z,
                              const float* __restrict__ h,
                              const float* __restrict__ raw_l)
{
    int idx = blockIdx.x * blockDim.x + threadIdx.x;
    if (idx >= OC * IDIM) return;
    int o = idx / IDIM;
    int i = idx % IDIM;

    float zf[PP];
    double hh[PP];
#pragma unroll
    for (int p = 0; p < PP; p++) {
        zf[p] = z[(o * IDIM + i) * PP + p];
        hh[p] = (double)h[(o * IDIM + i) * PP + p];
    }
    float rl  = raw_l[o * IDIM + i];
    float lf  = log1pf(expf(rl));        // softplus
    float l2f = lf * lf;
    float inv_l2f = 1.0f / l2f;

    // K = exp(-0.5 dz^2 / l2) + 1e-4 I   (fp32 entries, like the reference)
    double K[PP][PP];
#pragma unroll
    for (int a = 0; a < PP; a++) K[a][a] = 1.0 + 1e-4;
#pragma unroll
    for (int a = 0; a < PP; a++)
#pragma unroll
        for (int b = a + 1; b < PP; b++) {
            float d = zf[a] - zf[b];
            double e = (double)expf(-0.5f * d * d * inv_l2f);
            K[a][b] = e;
            K[b][a] = e;
        }

    // fp64 Cholesky: K = L L^T, keeping invdiag (no divisions)
    double L[PP][PP], invd[PP];
#pragma unroll
    for (int a = 0; a < PP; a++) {
        double s = K[a][a];
        for (int k = 0; k < a; k++) s -= L[a][k] * L[a][k];
        double rs = drsqrt(s);
        L[a][a] = s * rs;
        invd[a] = rs;
        for (int b = a + 1; b < PP; b++) {
            double t = K[b][a];
            for (int k = 0; k < a; k++) t -= L[b][k] * L[a][k];
            L[b][a] = t * rs;
        }
    }

    // Linv (lower triangular inverse of L)
    double Li[PP][PP];
#pragma unroll
    for (int c = 0; c < PP; c++) {
        for (int a = 0; a < PP; a++) {
            if (a < c) { Li[a][c] = 0.0; continue; }
            double t = (a == c) ? 1.0 : 0.0;
            for (int k = c; k < a; k++) t -= L[a][k] * Li[k][c];
            Li[a][c] = t * invd[a];
        }
    }

    // alpha = K^{-1} h via two triangular solves
    double t1[PP];
#pragma unroll
    for (int a = 0; a < PP; a++) {
        double t = hh[a];
        for (int k = 0; k < a; k++) t -= L[a][k] * t1[k];
        t1[a] = t * invd[a];
    }
    double alpha[PP];
    for (int a = PP - 1; a >= 0; a--) {
        double t = t1[a];
        for (int k = a + 1; k < PP; k++) t -= L[k][a] * alpha[k];
        alpha[a] = t * invd[a];
    }

    // Emit 26 duplicated pairs; sqrt(l2) folded into alpha and Linv.
    float vals[26];
    vals[0] = l2f;
#pragma unroll
    for (int p = 0; p < PP; p++) vals[1 + p] = -zf[p];
#pragma unroll
    for (int p = 0; p < PP; p++) vals[6 + p] = lf * (float)alpha[p];
    int k = 11;
#pragma unroll
    for (int a = 0; a < PP; a++)
#pragma unroll
        for (int b = 0; b <= a; b++) vals[k++] = lf * (float)Li[a][b];

    float* pp = &g_params[(i * OC + o) * RECF];
#pragma unroll
    for (int j = 0; j < 26; j++) { pp[2 * j] = vals[j]; pp[2 * j + 1] = vals[j]; }
}

// ---------------------------------------------------------------------------
// Per-pixel-pair GP math (packed f32x2, params by value in registers)
// ---------------------------------------------------------------------------
__device__ __forceinline__ void gp_pair(
    u64 mu2, u64 s22,
    ulonglong2 v0, ulonglong2 v1, ulonglong2 v2, ulonglong2 v3,
    ulonglong2 v4, ulonglong2 v5, ulonglong2 v6, ulonglong2 v7,
    ulonglong2 v8, ulonglong2 v9, ulonglong2 v10, ulonglong2 v11,
    ulonglong2 v12, u64 kneg, u64& accm, u64& accv)
{
    u64 d2    = add2(v0.x, s22);          // l2 + s2
    u64 rs2   = rsqrt_2(d2);              // 1/sqrt(d)
    u64 invd2 = mul2(rs2, rs2);           // 1/d
    u64 cc2   = mul2(kneg, invd2);

    u64 e0, e1, e2, e3, e4, df;
    df = add2(mu2, v0.y); e0 = ex2_2(mul2(mul2(df, df), cc2));
    df = add2(mu2, v1.x); e1 = ex2_2(mul2(mul2(df, df), cc2));
    df = add2(mu2, v1.y); e2 = ex2_2(mul2(mul2(df, df), cc2));
    df = add2(mu2, v2.x); e3 = ex2_2(mul2(mul2(df, df), cc2));
    df = add2(mu2, v2.y); e4 = ex2_2(mul2(mul2(df, df), cc2));

    // mean: rsqrt(d) * (e . alpha')      [alpha' = sqrt(l2)*alpha]
    u64 md = mul2(e0, v3.x);
    md = fma2(e1, v3.y, md);
    md = fma2(e2, v4.x, md);
    md = fma2(e3, v4.y, md);
    md = fma2(e4, v5.x, md);
    accm = fma2(rs2, md, accm);

    // var: (1/d) * || L' e ||^2          [L' = sqrt(l2)*Linv]
    u64 w0 = mul2(v5.y, e0);
    u64 w1 = fma2(v6.y, e1, mul2(v6.x, e0));
    u64 w2 = fma2(v8.x, e2, fma2(v7.y, e1, mul2(v7.x, e0)));
    u64 w3 = fma2(v10.x, e3, fma2(v9.y, e2, fma2(v9.x, e1, mul2(v8.y, e0))));
    u64 w4 = fma2(v12.y, e4, fma2(v12.x, e3,
             fma2(v11.y, e2, fma2(v11.x, e1, mul2(v10.y, e0)))));
    u64 vd = mul2(w0, w0);
    vd = fma2(w1, w1, vd);
    vd = fma2(w2, w2, vd);
    vd = fma2(w3, w3, vd);
    vd = fma2(w4, w4, vd);
    accv = fma2(invd2, vd, accv);
}

// ---------------------------------------------------------------------------
// Kernel 2: main GP moment propagation, packed f32x2, 4 pixels per thread.
// CTA = 128 threads = 4 warps = ONE output channel x 4 input-channel quarters,
// covering 128 pixels (4 ow-rows; 2 f32x2 pairs per thread lane).
// Grid = 64 pixel-groups x 16 channels = 1024 CTAs; ~4 CTAs/SM (reg-bound).
// Param LDS.128s amortize over 4 pixels (halves L1/LDS rate vs 2px/thread).
// ---------------------------------------------------------------------------
#define TROW 306           // 34 * 9 float2 per tile row
__global__ __launch_bounds__(128, 4) void gp_main(const float* __restrict__ xm,
                                                  const float* __restrict__ xv,
                                                  float* __restrict__ out)
{
    __shared__ ulonglong2 s_par[IDIM * RECQ];     // 14976 B
    __shared__ float2     s_tile[6 * TROW];       // 14688 B, (m,v) interleaved
    __shared__ u64        red_mA[3][32], red_vA[3][32];
    __shared__ u64        red_mB[3][32], red_vB[3][32];

    const int tid  = threadIdx.x;
    const int warp = tid >> 5;
    const int lane = tid & 31;

    const int g    = blockIdx.x >> 4;          // 64 pixel groups of 128
    const int o    = blockIdx.x & 15;          // output channel
    const int base = g * 128;
    const int n    = base >> 10;
    const int oh0  = (base >> 5) & 31;         // multiple of 4

    // ---- stage param table for this o: 72 records x 13 ulonglong2 ----
    {
        const ulonglong2* __restrict__ gp = (const ulonglong2*)g_params;
        for (int j = tid; j < IDIM * RECQ; j += 128) {
            int i = j / RECQ;
            int q = j - i * RECQ;
            s_par[j] = gp[(i * OC + o) * RECQ + q];
        }
    }

    // ---- zero tile, then fill interior rows with float4 gmem loads ----
    for (int j = tid; j < 6 * TROW; j += 128) s_tile[j] = make_float2(0.0f, 0.0f);
    __syncthreads();
    for (int j = tid; j < 6 * 64; j += 128) {
        int t    = j >> 6;                 // tile row 0..5  -> y = oh0-1+t
        int r    = j & 63;
        int x    = r >> 1;
        int half = (r & 1) * 4;
        int y    = oh0 - 1 + t;
        if ((unsigned)y < 32u) {
            const float4 m4 = *(const float4*)&xm[(((n * IHW + y) * IHW + x) * IC) + half];
            const float4 v4 = *(const float4*)&xv[(((n * IHW + y) * IHW + x) * IC) + half];
            int b = t * TROW + (x + 1) * 9 + half;
            s_tile[b + 0] = make_float2(m4.x, v4.x);
            s_tile[b + 1] = make_float2(m4.y, v4.y);
            s_tile[b + 2] = make_float2(m4.z, v4.z);
            s_tile[b + 3] = make_float2(m4.w, v4.w);
        }
    }
    __syncthreads();

    const u64 kneg = pk2(-0.7213475204f, -0.7213475204f);  // -0.5*log2(e)
    u64 accmA = 0ull, accvA = 0ull;    // pixel rows oh0, oh0+1
    u64 accmB = 0ull, accvB = 0ull;    // pixel rows oh0+2, oh0+3

    const float2* __restrict__ bt = s_tile + lane * 9;

#pragma unroll
    for (int cc = 0; cc < 2; cc++) {
        const int c = warp * 2 + cc;       // input channel (warp-uniform)
        const ulonglong2* __restrict__ sp = s_par + c * 9 * RECQ;
#pragma unroll
        for (int k9 = 0; k9 < 9; k9++) {
            const int kh = k9 / 3;
            const int kw = k9 % 3;

            const ulonglong2* pp = sp + k9 * RECQ;
            ulonglong2 v0 = pp[0],  v1 = pp[1],  v2 = pp[2],  v3 = pp[3];
            ulonglong2 v4 = pp[4],  v5 = pp[5],  v6 = pp[6];
            ulonglong2 v7 = pp[7],  v8 = pp[8],  v9 = pp[9],  v10 = pp[10];
            ulonglong2 v11 = pp[11], v12 = pp[12];

            const int off = kh * TROW + kw * 9 + c;
            float2 r0 = bt[off];               // pixel row oh0
            float2 r1 = bt[off + TROW];        // pixel row oh0+1
            float2 r2 = bt[off + 2 * TROW];    // pixel row oh0+2
            float2 r3 = bt[off + 3 * TROW];    // pixel row oh0+3

            gp_pair(pk2(r0.x, r1.x), pk2(r0.y, r1.y),
                    v0, v1, v2, v3, v4, v5, v6, v7, v8, v9, v10, v11, v12,
                    kneg, accmA, accvA);
            gp_pair(pk2(r2.x, r3.x), pk2(r2.y, r3.y),
                    v0, v1, v2, v3, v4, v5, v6, v7, v8, v9, v10, v11, v12,
                    kneg, accmB, accvB);
        }
    }

    // ---- reduce the 4 input-channel quarters, warp 0 writes ----
    if (warp) {
        red_mA[warp - 1][lane] = accmA;
        red_vA[warp - 1][lane] = accvA;
        red_mB[warp - 1][lane] = accmB;
        red_vB[warp - 1][lane] = accvB;
    }
    __syncthreads();
    if (warp == 0) {
        accmA = add2(accmA, add2(red_mA[0][lane], add2(red_mA[1][lane], red_mA[2][lane])));
        accvA = add2(accvA, add2(red_vA[0][lane], add2(red_vA[1][lane], red_vA[2][lane])));
        accmB = add2(accmB, add2(red_mB[0][lane], add2(red_mB[1][lane], red_mB[2][lane])));
        accvB = add2(accvB, add2(red_vB[0][lane], add2(red_vB[1][lane], red_vB[2][lane])));

        float m0, m1, m2, m3, q0, q1, q2, q3;
        upk2(accmA, m0, m1);
        upk2(accmB, m2, m3);
        upk2(accvA, q0, q1);
        upk2(accvB, q2, q3);
        const int r0 = base + lane;
        out[r0 * OC + o]                       = m0;
        out[(r0 + 32) * OC + o]                = m1;
        out[(r0 + 64) * OC + o]                = m2;
        out[(r0 + 96) * OC + o]                = m3;
        out[NROWS * OC + r0 * OC + o]          = fmaxf(72.0f - q0, 1e-6f);
        out[NROWS * OC + (r0 + 32) * OC + o]   = fmaxf(72.0f - q1, 1e-6f);
        out[NROWS * OC + (r0 + 64) * OC + o]   = fmaxf(72.0f - q2, 1e-6f);
        out[NROWS * OC + (r0 + 96) * OC + o]   = fmaxf(72.0f - q3, 1e-6f);
    }
}

// ---------------------------------------------------------------------------
extern "C" void kernel_launch(void* const* d_in, const int* in_sizes, int n_in,
                              void* d_out, int out_size)
{
    const float* xm    = (const float*)d_in[0];  // x_mean [8,32,32,8]
    const float* xv    = (const float*)d_in[1];  // x_var  [8,32,32,8]
    const float* z     = (const float*)d_in[2];  // [16,72,5]
    const float* h     = (const float*)d_in[3];  // [16,72,5]
    const float* raw_l = (const float*)d_in[4];  // [16,72]
    float* out = (float*)d_out;                  // [mean(131072), var(131072)]

    gp_precompute<<<(OC * IDIM + 127) / 128, 128>>>(z, h, raw_l);
    gp_main<<<1024, 128>>>(xm, xv, out);
}

// round 9
// speedup vs baseline: 1.1389x; 1.1389x over previous
#include <cuda_runtime.h>

typedef unsigned long long u64;

// Problem constants
#define IHW   32
#define IC    8
#define OC    16
#define PP    5
#define IDIM  72            // IC*3*3
#define NROWS 8192          // N*OH*OW = 8*32*32
#define RECF  52            // floats per (i,o) record: 26 duplicated pairs
#define RECQ  13            // ulonglong2 per record

// Precomputed per-(i,o) params, duplicated pairs for f32x2 consumption.
// pair order: l2, -z0..-z4, a'0..a'4 (= sqrt(l2)*alpha),
//             L'00..L'44 (= sqrt(l2)*Linv lower tri row-major, 15 vals)
__device__ float g_params[IDIM * OC * RECF];

// ---------------------------------------------------------------------------
// f32x2 helpers (sm_103a packed fp32)
// ---------------------------------------------------------------------------
__device__ __forceinline__ u64 pk2(float a, float b) {
    u64 r; asm("mov.b64 %0, {%1, %2};" : "=l"(r) : "f"(a), "f"(b)); return r;
}
__device__ __forceinline__ void upk2(u64 v, float& a, float& b) {
    asm("mov.b64 {%0, %1}, %2;" : "=f"(a), "=f"(b) : "l"(v));
}
__device__ __forceinline__ u64 fma2(u64 a, u64 b, u64 c) {
    u64 r; asm("fma.rn.f32x2 %0, %1, %2, %3;" : "=l"(r) : "l"(a), "l"(b), "l"(c)); return r;
}
__device__ __forceinline__ u64 mul2(u64 a, u64 b) {
    u64 r; asm("mul.rn.f32x2 %0, %1, %2;" : "=l"(r) : "l"(a), "l"(b)); return r;
}
__device__ __forceinline__ u64 add2(u64 a, u64 b) {
    u64 r; asm("add.rn.f32x2 %0, %1, %2;" : "=l"(r) : "l"(a), "l"(b)); return r;
}
__device__ __forceinline__ u64 ex2_2(u64 v) {
    float a, b; upk2(v, a, b);
    asm("ex2.approx.ftz.f32 %0, %0;" : "+f"(a));
    asm("ex2.approx.ftz.f32 %0, %0;" : "+f"(b));
    return pk2(a, b);
}
__device__ __forceinline__ u64 rsqrt_2(u64 v) {
    float a, b; upk2(v, a, b);
    asm("rsqrt.approx.ftz.f32 %0, %0;" : "+f"(a));
    asm("rsqrt.approx.ftz.f32 %0, %0;" : "+f"(b));
    return pk2(a, b);
}

// fp64 reciprocal-sqrt without divisions: float MUFU seed + 2 Newton iters
__device__ __forceinline__ double drsqrt(double x)
{
    float xf = (float)x, yf;
    asm("rsqrt.approx.ftz.f32 %0, %1;" : "=f"(yf) : "f"(xf));
    double y = (double)yf;
    y = y * (1.5 - 0.5 * x * y * y);
    y = y * (1.5 - 0.5 * x * y * y);
    return y;
}

// ---------------------------------------------------------------------------
// Kernel 1: per-neuron precompute, 32-thread CTAs spread across 36 SMs
// (B300 DFMA throughput is per-SM-shared; 9x128 packed 4 warps onto 9 SMs).
// fp32 softplus + K-matrix exps (matches fp32 reference K); fp64 5x5 solves.
// ---------------------------------------------------------------------------
__global__ __launch_bounds__(32) void gp_precompute(const float* __restrict__ z,
                                                    const float* __restrict__ h,
                                                    const float* __restrict__ raw_l)
{
    int idx = blockIdx.x * 32 + threadIdx.x;
    if (idx >= OC * IDIM) return;
    int o = idx / IDIM;
    int i = idx % IDIM;

    float zf[PP];
    double hh[PP];
#pragma unroll
    for (int p = 0; p < PP; p++) {
        zf[p] = z[(o * IDIM + i) * PP + p];
        hh[p] = (double)h[(o * IDIM + i) * PP + p];
    }
    float rl  = raw_l[o * IDIM + i];
    float lf  = log1pf(expf(rl));        // softplus
    float l2f = lf * lf;
    float inv_l2f = 1.0f / l2f;

    // K = exp(-0.5 dz^2 / l2) + 1e-4 I   (fp32 entries, like the reference)
    double K[PP][PP];
#pragma unroll
    for (int a = 0; a < PP; a++) K[a][a] = 1.0 + 1e-4;
#pragma unroll
    for (int a = 0; a < PP; a++)
#pragma unroll
        for (int b = a + 1; b < PP; b++) {
            float d = zf[a] - zf[b];
            double e = (double)expf(-0.5f * d * d * inv_l2f);
            K[a][b] = e;
            K[b][a] = e;
        }

    // fp64 Cholesky: K = L L^T, keeping invdiag (no divisions)
    double L[PP][PP], invd[PP];
#pragma unroll
    for (int a = 0; a < PP; a++) {
        double s = K[a][a];
        for (int k = 0; k < a; k++) s -= L[a][k] * L[a][k];
        double rs = drsqrt(s);
        L[a][a] = s * rs;
        invd[a] = rs;
        for (int b = a + 1; b < PP; b++) {
            double t = K[b][a];
            for (int k = 0; k < a; k++) t -= L[b][k] * L[a][k];
            L[b][a] = t * rs;
        }
    }

    // Linv (lower triangular inverse of L)
    double Li[PP][PP];
#pragma unroll
    for (int c = 0; c < PP; c++) {
        for (int a = 0; a < PP; a++) {
            if (a < c) { Li[a][c] = 0.0; continue; }
            double t = (a == c) ? 1.0 : 0.0;
            for (int k = c; k < a; k++) t -= L[a][k] * Li[k][c];
            Li[a][c] = t * invd[a];
        }
    }

    // alpha = K^{-1} h via two triangular solves
    double t1[PP];
#pragma unroll
    for (int a = 0; a < PP; a++) {
        double t = hh[a];
        for (int k = 0; k < a; k++) t -= L[a][k] * t1[k];
        t1[a] = t * invd[a];
    }
    double alpha[PP];
    for (int a = PP - 1; a >= 0; a--) {
        double t = t1[a];
        for (int k = a + 1; k < PP; k++) t -= L[k][a] * alpha[k];
        alpha[a] = t * invd[a];
    }

    // Emit 26 duplicated pairs; sqrt(l2) folded into alpha and Linv.
    float vals[26];
    vals[0] = l2f;
#pragma unroll
    for (int p = 0; p < PP; p++) vals[1 + p] = -zf[p];
#pragma unroll
    for (int p = 0; p < PP; p++) vals[6 + p] = lf * (float)alpha[p];
    int k = 11;
#pragma unroll
    for (int a = 0; a < PP; a++)
#pragma unroll
        for (int b = 0; b <= a; b++) vals[k++] = lf * (float)Li[a][b];

    float* pp = &g_params[(i * OC + o) * RECF];
#pragma unroll
    for (int j = 0; j < 26; j++) { pp[2 * j] = vals[j]; pp[2 * j + 1] = vals[j]; }
}

// ---------------------------------------------------------------------------
// Kernel 2: main GP moment propagation, packed f32x2, 4 pixels per thread,
// staged param loads (l2/z -> exps; alpha -> mean; L -> var) so param
// registers stream instead of staying live; both pixel-pairs interleaved
// so the MUFU work issues as one burst per iteration.
// CTA = 128 threads = 4 warps = ONE output channel x 4 input-channel quarters,
// covering 128 pixels (4 ow-rows; 2 f32x2 pairs per thread lane).
// Grid = 64 pixel-groups x 16 channels = 1024 CTAs.
// ---------------------------------------------------------------------------
#define TROW 306           // 34 * 9 float2 per tile row
__global__ __launch_bounds__(128, 5) void gp_main(const float* __restrict__ xm,
                                                  const float* __restrict__ xv,
                                                  float* __restrict__ out)
{
    __shared__ ulonglong2 s_par[IDIM * RECQ];     // 14976 B
    __shared__ float2     s_tile[6 * TROW];       // 14688 B, (m,v) interleaved
    __shared__ u64        red_mA[3][32], red_vA[3][32];
    __shared__ u64        red_mB[3][32], red_vB[3][32];

    const int tid  = threadIdx.x;
    const int warp = tid >> 5;
    const int lane = tid & 31;

    const int g    = blockIdx.x >> 4;          // 64 pixel groups of 128
    const int o    = blockIdx.x & 15;          // output channel
    const int base = g * 128;
    const int n    = base >> 10;
    const int oh0  = (base >> 5) & 31;         // multiple of 4

    // ---- stage param table for this o: 72 records x 13 ulonglong2 ----
    {
        const ulonglong2* __restrict__ gp = (const ulonglong2*)g_params;
        for (int j = tid; j < IDIM * RECQ; j += 128) {
            int i = j / RECQ;
            int q = j - i * RECQ;
            s_par[j] = gp[(i * OC + o) * RECQ + q];
        }
    }

    // ---- zero tile, then fill interior rows with float4 gmem loads ----
    for (int j = tid; j < 6 * TROW; j += 128) s_tile[j] = make_float2(0.0f, 0.0f);
    __syncthreads();
    for (int j = tid; j < 6 * 64; j += 128) {
        int t    = j >> 6;                 // tile row 0..5  -> y = oh0-1+t
        int r    = j & 63;
        int x    = r >> 1;
        int half = (r & 1) * 4;
        int y    = oh0 - 1 + t;
        if ((unsigned)y < 32u) {
            const float4 m4 = *(const float4*)&xm[(((n * IHW + y) * IHW + x) * IC) + half];
            const float4 v4 = *(const float4*)&xv[(((n * IHW + y) * IHW + x) * IC) + half];
            int b = t * TROW + (x + 1) * 9 + half;
            s_tile[b + 0] = make_float2(m4.x, v4.x);
            s_tile[b + 1] = make_float2(m4.y, v4.y);
            s_tile[b + 2] = make_float2(m4.z, v4.z);
            s_tile[b + 3] = make_float2(m4.w, v4.w);
        }
    }
    __syncthreads();

    const u64 kneg = pk2(-0.7213475204f, -0.7213475204f);  // -0.5*log2(e)
    u64 accmA = 0ull, accvA = 0ull;    // pixel rows oh0, oh0+1
    u64 accmB = 0ull, accvB = 0ull;    // pixel rows oh0+2, oh0+3

    const float2* __restrict__ bt = s_tile + lane * 9;

#pragma unroll
    for (int cc = 0; cc < 2; cc++) {
        const int c = warp * 2 + cc;       // input channel (warp-uniform)
        const ulonglong2* __restrict__ sp = s_par + c * 9 * RECQ;
#pragma unroll
        for (int k9 = 0; k9 < 9; k9++) {
            const int kh = k9 / 3;
            const int kw = k9 % 3;
            const ulonglong2* pp = sp + k9 * RECQ;

            // ---- stage 0: pixel data ----
            const int off = kh * TROW + kw * 9 + c;
            float2 r0 = bt[off];               // pixel row oh0
            float2 r1 = bt[off + TROW];        // pixel row oh0+1
            float2 r2 = bt[off + 2 * TROW];    // pixel row oh0+2
            float2 r3 = bt[off + 3 * TROW];    // pixel row oh0+3
            u64 muA = pk2(r0.x, r1.x), s2A = pk2(r0.y, r1.y);
            u64 muB = pk2(r2.x, r3.x), s2B = pk2(r2.y, r3.y);

            // ---- stage 1: l2 + z -> MUFU burst (both pairs) ----
            ulonglong2 v0 = pp[0], v1 = pp[1], v2 = pp[2];

            u64 dA    = add2(v0.x, s2A);
            u64 dB    = add2(v0.x, s2B);
            u64 rsA   = rsqrt_2(dA);
            u64 rsB   = rsqrt_2(dB);
            u64 invdA = mul2(rsA, rsA);
            u64 invdB = mul2(rsB, rsB);
            u64 ccA   = mul2(kneg, invdA);
            u64 ccB   = mul2(kneg, invdB);

            u64 eA0, eA1, eA2, eA3, eA4, eB0, eB1, eB2, eB3, eB4, df;
            df = add2(muA, v0.y); eA0 = ex2_2(mul2(mul2(df, df), ccA));
            df = add2(muB, v0.y); eB0 = ex2_2(mul2(mul2(df, df), ccB));
            df = add2(muA, v1.x); eA1 = ex2_2(mul2(mul2(df, df), ccA));
            df = add2(muB, v1.x); eB1 = ex2_2(mul2(mul2(df, df), ccB));
            df = add2(muA, v1.y); eA2 = ex2_2(mul2(mul2(df, df), ccA));
            df = add2(muB, v1.y); eB2 = ex2_2(mul2(mul2(df, df), ccB));
            df = add2(muA, v2.x); eA3 = ex2_2(mul2(mul2(df, df), ccA));
            df = add2(muB, v2.x); eB3 = ex2_2(mul2(mul2(df, df), ccB));
            df = add2(muA, v2.y); eA4 = ex2_2(mul2(mul2(df, df), ccA));
            df = add2(muB, v2.y); eB4 = ex2_2(mul2(mul2(df, df), ccB));

            // ---- stage 2: alpha' -> mean dots ----
            {
                ulonglong2 v3 = pp[3], v4 = pp[4];
                u64 a0 = v3.x, a1 = v3.y, a2 = v4.x, a3 = v4.y;
                u64 mdA = mul2(eA0, a0);
                u64 mdB = mul2(eB0, a0);
                mdA = fma2(eA1, a1, mdA);
                mdB = fma2(eB1, a1, mdB);
                mdA = fma2(eA2, a2, mdA);
                mdB = fma2(eB2, a2, mdB);
                mdA = fma2(eA3, a3, mdA);
                mdB = fma2(eB3, a3, mdB);
                ulonglong2 v5 = pp[5];
                mdA = fma2(eA4, v5.x, mdA);
                mdB = fma2(eB4, v5.x, mdB);
                accmA = fma2(rsA, mdA, accmA);
                accmB = fma2(rsB, mdB, accmB);

                // ---- stage 3: L' rows -> var ----
                u64 L00 = v5.y;
                u64 wA0 = mul2(L00, eA0);
                u64 wB0 = mul2(L00, eB0);
                u64 vdA = mul2(wA0, wA0);
                u64 vdB = mul2(wB0, wB0);

                ulonglong2 v6 = pp[6];
                u64 wA1 = fma2(v6.y, eA1, mul2(v6.x, eA0));
                u64 wB1 = fma2(v6.y, eB1, mul2(v6.x, eB0));
                vdA = fma2(wA1, wA1, vdA);
                vdB = fma2(wB1, wB1, vdB);

                ulonglong2 v7 = pp[7], v8 = pp[8];
                u64 wA2 = fma2(v8.x, eA2, fma2(v7.y, eA1, mul2(v7.x, eA0)));
                u64 wB2 = fma2(v8.x, eB2, fma2(v7.y, eB1, mul2(v7.x, eB0)));
                vdA = fma2(wA2, wA2, vdA);
                vdB = fma2(wB2, wB2, vdB);

                ulonglong2 v9 = pp[9], v10 = pp[10];
                u64 wA3 = fma2(v10.x, eA3, fma2(v9.y, eA2, fma2(v9.x, eA1, mul2(v8.y, eA0))));
                u64 wB3 = fma2(v10.x, eB3, fma2(v9.y, eB2, fma2(v9.x, eB1, mul2(v8.y, eB0))));
                vdA = fma2(wA3, wA3, vdA);
                vdB = fma2(wB3, wB3, vdB);

                ulonglong2 v11 = pp[11], v12 = pp[12];
                u64 wA4 = fma2(v12.y, eA4, fma2(v12.x, eA3,
                          fma2(v11.y, eA2, fma2(v11.x, eA1, mul2(v10.y, eA0)))));
                u64 wB4 = fma2(v12.y, eB4, fma2(v12.x, eB3,
                          fma2(v11.y, eB2, fma2(v11.x, eB1, mul2(v10.y, eB0)))));
                vdA = fma2(wA4, wA4, vdA);
                vdB = fma2(wB4, wB4, vdB);

                accvA = fma2(invdA, vdA, accvA);
                accvB = fma2(invdB, vdB, accvB);
            }
        }
    }

    // ---- reduce the 4 input-channel quarters, warp 0 writes ----
    if (warp) {
        red_mA[warp - 1][lane] = accmA;
        red_vA[warp - 1][lane] = accvA;
        red_mB[warp - 1][lane] = accmB;
        red_vB[warp - 1][lane] = accvB;
    }
    __syncthreads();
    if (warp == 0) {
        accmA = add2(accmA, add2(red_mA[0][lane], add2(red_mA[1][lane], red_mA[2][lane])));
        accvA = add2(accvA, add2(red_vA[0][lane], add2(red_vA[1][lane], red_vA[2][lane])));
        accmB = add2(accmB, add2(red_mB[0][lane], add2(red_mB[1][lane], red_mB[2][lane])));
        accvB = add2(accvB, add2(red_vB[0][lane], add2(red_vB[1][lane], red_vB[2][lane])));

        float m0, m1, m2, m3, q0, q1, q2, q3;
        upk2(accmA, m0, m1);
        upk2(accmB, m2, m3);
        upk2(accvA, q0, q1);
        upk2(accvB, q2, q3);
        const int r0 = base + lane;
        out[r0 * OC + o]                       = m0;
        out[(r0 + 32) * OC + o]                = m1;
        out[(r0 + 64) * OC + o]                = m2;
        out[(r0 + 96) * OC + o]                = m3;
        out[NROWS * OC + r0 * OC + o]          = fmaxf(72.0f - q0, 1e-6f);
        out[NROWS * OC + (r0 + 32) * OC + o]   = fmaxf(72.0f - q1, 1e-6f);
        out[NROWS * OC + (r0 + 64) * OC + o]   = fmaxf(72.0f - q2, 1e-6f);
        out[NROWS * OC + (r0 + 96) * OC + o]   = fmaxf(72.0f - q3, 1e-6f);
    }
}

// ---------------------------------------------------------------------------
extern "C" void kernel_launch(void* const* d_in, const int* in_sizes, int n_in,
                              void* d_out, int out_size)
{
    const float* xm    = (const float*)d_in[0];  // x_mean [8,32,32,8]
    const float* xv    = (const float*)d_in[1];  // x_var  [8,32,32,8]
    const float* z     = (const float*)d_in[2];  // [16,72,5]
    const float* h     = (const float*)d_in[3];  // [16,72,5]
    const float* raw_l = (const float*)d_in[4];  // [16,72]
    float* out = (float*)d_out;                  // [mean(131072), var(131072)]

    gp_precompute<<<36, 32>>>(z, h, raw_l);
    gp_main<<<1024, 128>>>(xm, xv, out);
}